// round 2
// baseline (speedup 1.0000x reference)
#include <cuda_runtime.h>
#include <cuda_bf16.h>

#define NDIM 128
#define MAX_NODES 100000

// Scratch: z[n] = W @ x_target[n]  (51.2 MB), transposed W (64 KB), dtype flag.
__device__ float g_z[MAX_NODES * NDIM];
__device__ float g_Wt[NDIM * NDIM];
__device__ int   g_idx_is64;

// ---------------------------------------------------------------------------
// Kernel 0: detect index dtype. If the buffer holds int64 values < 2^31, every
// odd 32-bit word is 0. For int32 index data, odd words are random indices.
// ---------------------------------------------------------------------------
__global__ void detect_idx_kernel(const int* __restrict__ idx_words, int nwords) {
    // single block, 256 threads; check odd words in the first nwords
    __shared__ int s_any_nonzero;
    if (threadIdx.x == 0) s_any_nonzero = 0;
    __syncthreads();
    for (int i = 1 + 2 * threadIdx.x; i < nwords; i += 2 * blockDim.x) {
        if (idx_words[i] != 0) { s_any_nonzero = 1; break; }
    }
    __syncthreads();
    if (threadIdx.x == 0) g_idx_is64 = (s_any_nonzero == 0) ? 1 : 0;
}

// ---------------------------------------------------------------------------
// Kernel 1: transpose W (128x128): g_Wt[f*128 + d] = W[d*128 + f]
// ---------------------------------------------------------------------------
__global__ void transpose_W_kernel(const float* __restrict__ W) {
    int d = blockIdx.x;
    int f = threadIdx.x;
    g_Wt[f * NDIM + d] = W[d * NDIM + f];
}

// ---------------------------------------------------------------------------
// Kernel 2: z = x_target @ W^T   (z[n,d] = sum_f W[d,f] * xt[n,f])
// 256 threads = 8 warps; 32 rows/block (4 rows/warp); 4 cols/lane.
// ---------------------------------------------------------------------------
__global__ void __launch_bounds__(256) gemm_zt_kernel(const float* __restrict__ xt,
                                                      int n_rows) {
    __shared__ float s_x[32][NDIM];

    const int warp = threadIdx.x >> 5;
    const int lane = threadIdx.x & 31;
    const int base = blockIdx.x * 32;

    for (int i = threadIdx.x; i < 32 * NDIM; i += blockDim.x) {
        int r = i >> 7;
        int c = i & (NDIM - 1);
        int row = base + r;
        s_x[r][c] = (row < n_rows) ? xt[(size_t)row * NDIM + c] : 0.0f;
    }
    __syncthreads();

    const int r0  = warp * 4;
    const int col = lane * 4;

    float4 a0 = make_float4(0.f, 0.f, 0.f, 0.f);
    float4 a1 = a0, a2 = a0, a3 = a0;

#define FMA_ROW(acc, xv)                                             \
    acc.x += xv.x * w0.x + xv.y * w1.x + xv.z * w2.x + xv.w * w3.x;  \
    acc.y += xv.x * w0.y + xv.y * w1.y + xv.z * w2.y + xv.w * w3.y;  \
    acc.z += xv.x * w0.z + xv.y * w1.z + xv.z * w2.z + xv.w * w3.z;  \
    acc.w += xv.x * w0.w + xv.y * w1.w + xv.z * w2.w + xv.w * w3.w;

#pragma unroll 8
    for (int f = 0; f < NDIM; f += 4) {
        float4 w0 = *(const float4*)(g_Wt + (f + 0) * NDIM + col);
        float4 w1 = *(const float4*)(g_Wt + (f + 1) * NDIM + col);
        float4 w2 = *(const float4*)(g_Wt + (f + 2) * NDIM + col);
        float4 w3 = *(const float4*)(g_Wt + (f + 3) * NDIM + col);

        float4 x0 = *(const float4*)&s_x[r0 + 0][f];
        float4 x1 = *(const float4*)&s_x[r0 + 1][f];
        float4 x2 = *(const float4*)&s_x[r0 + 2][f];
        float4 x3 = *(const float4*)&s_x[r0 + 3][f];

        FMA_ROW(a0, x0)
        FMA_ROW(a1, x1)
        FMA_ROW(a2, x2)
        FMA_ROW(a3, x3)
    }
#undef FMA_ROW

    int row;
    row = base + r0 + 0; if (row < n_rows) *(float4*)(g_z + (size_t)row * NDIM + col) = a0;
    row = base + r0 + 1; if (row < n_rows) *(float4*)(g_z + (size_t)row * NDIM + col) = a1;
    row = base + r0 + 2; if (row < n_rows) *(float4*)(g_z + (size_t)row * NDIM + col) = a2;
    row = base + r0 + 3; if (row < n_rows) *(float4*)(g_z + (size_t)row * NDIM + col) = a3;
}

// ---------------------------------------------------------------------------
// Kernel 3: per-edge dot. One warp per edge, dtype-flexible index load.
// ---------------------------------------------------------------------------
__global__ void __launch_bounds__(256) edge_dot_kernel(
    const float* __restrict__ xs,
    const void* __restrict__ eli_raw,
    const float* __restrict__ bias,
    float* __restrict__ out,
    int E, int N) {
    int gwarp = (blockIdx.x * blockDim.x + threadIdx.x) >> 5;
    int lane  = threadIdx.x & 31;
    if (gwarp >= E) return;

    long long s, t;
    if (g_idx_is64) {
        const long long* eli = (const long long*)eli_raw;
        s = __ldg(&eli[gwarp]);
        t = __ldg(&eli[(long long)E + gwarp]);
    } else {
        const int* eli = (const int*)eli_raw;
        s = __ldg(&eli[gwarp]);
        t = __ldg(&eli[(long long)E + gwarp]);
    }
    // defensive clamp: never fault even if dtype detection were wrong
    if (s < 0) s = 0; if (s >= N) s = N - 1;
    if (t < 0) t = 0; if (t >= N) t = N - 1;

    const float4 a = *(const float4*)(xs  + (size_t)s * NDIM + lane * 4);
    const float4 v = *(const float4*)(g_z + (size_t)t * NDIM + lane * 4);

    float acc = a.x * v.x + a.y * v.y + a.z * v.z + a.w * v.w;

#pragma unroll
    for (int o = 16; o > 0; o >>= 1)
        acc += __shfl_down_sync(0xFFFFFFFFu, acc, o);

    if (lane == 0) out[gwarp] = acc + __ldg(bias);
}

// ---------------------------------------------------------------------------
extern "C" void kernel_launch(void* const* d_in, const int* in_sizes, int n_in,
                              void* d_out, int out_size) {
    // Identify inputs by element count (robust to metadata ordering):
    //   W: 128*128 = 16384; b: 1; edges: 2*E (= out_size*2); x_*: N*128 (two of them)
    const float* x_source = nullptr;
    const float* x_target = nullptr;
    const void*  eli      = nullptr;
    const float* W        = nullptr;
    const float* bias     = nullptr;
    int N = 0;
    const int E = out_size;

    for (int i = 0; i < n_in; i++) {
        int sz = in_sizes[i];
        if (sz == NDIM * NDIM) {
            W = (const float*)d_in[i];
        } else if (sz == 1) {
            bias = (const float*)d_in[i];
        } else if (sz == 2 * E) {
            eli = d_in[i];
        } else {
            // feature matrix; first one seen = x_source, second = x_target
            if (!x_source) { x_source = (const float*)d_in[i]; N = sz / NDIM; }
            else           { x_target = (const float*)d_in[i]; }
        }
    }

    float* out = (float*)d_out;

    // 0) detect index dtype (checks first 4096 32-bit words)
    int nwords = 2 * E; if (nwords > 4096) nwords = 4096;
    detect_idx_kernel<<<1, 256>>>((const int*)eli, nwords);

    // 1) Wt = W^T
    transpose_W_kernel<<<NDIM, NDIM>>>(W);

    // 2) z = x_target @ W^T
    gemm_zt_kernel<<<(N + 31) / 32, 256>>>(x_target, N);

    // 3) per-edge gather + dot
    int nblocks = (E + 7) / 8;
    edge_dot_kernel<<<nblocks, 256>>>(x_source, eli, bias, out, E, N);
}

// round 3
// speedup vs baseline: 1.8976x; 1.8976x over previous
#include <cuda_runtime.h>
#include <cuda_fp16.h>

#define NDIM 128
#define MAX_NODES 100000

// Scratch: fp16 z table, fp16 x_source copy, transposed W, idx dtype flag.
__device__ __half g_z_h[MAX_NODES * NDIM];    // 25.6 MB
__device__ __half g_xs_h[MAX_NODES * NDIM];   // 25.6 MB
__device__ float  g_Wt[NDIM * NDIM];
__device__ int    g_idx_is64;

// ---------------------------------------------------------------------------
// Kernel 0: detect index dtype (int64 values < 2^31 -> all odd words zero).
// ---------------------------------------------------------------------------
__global__ void detect_idx_kernel(const int* __restrict__ idx_words, int nwords) {
    __shared__ int s_any_nonzero;
    if (threadIdx.x == 0) s_any_nonzero = 0;
    __syncthreads();
    for (int i = 1 + 2 * threadIdx.x; i < nwords; i += 2 * blockDim.x) {
        if (idx_words[i] != 0) { s_any_nonzero = 1; break; }
    }
    __syncthreads();
    if (threadIdx.x == 0) g_idx_is64 = (s_any_nonzero == 0) ? 1 : 0;
}

// ---------------------------------------------------------------------------
// Kernel 1: transpose W: g_Wt[f*128 + d] = W[d*128 + f]
// ---------------------------------------------------------------------------
__global__ void transpose_W_kernel(const float* __restrict__ W) {
    int d = blockIdx.x;
    int f = threadIdx.x;
    g_Wt[f * NDIM + d] = W[d * NDIM + f];
}

// ---------------------------------------------------------------------------
// Kernel 2: convert x_source -> fp16 (vectorized: 4 floats -> 4 halves/thread)
// ---------------------------------------------------------------------------
__global__ void __launch_bounds__(256) convert_xs_kernel(const float* __restrict__ xs,
                                                         int n_elem4) {
    int i = blockIdx.x * blockDim.x + threadIdx.x;
    if (i >= n_elem4) return;
    float4 v = *(const float4*)(xs + (size_t)i * 4);
    __half2 h0 = __floats2half2_rn(v.x, v.y);
    __half2 h1 = __floats2half2_rn(v.z, v.w);
    *(__half2*)(g_xs_h + (size_t)i * 4)     = h0;
    *(__half2*)(g_xs_h + (size_t)i * 4 + 2) = h1;
}

// ---------------------------------------------------------------------------
// Kernel 3: z = x_target @ W^T  (fp32 compute, fp16 store)
// 256 threads = 8 warps; 32 rows/block (4 rows/warp); 4 cols/lane.
// ---------------------------------------------------------------------------
__global__ void __launch_bounds__(256) gemm_zt_kernel(const float* __restrict__ xt,
                                                      int n_rows) {
    __shared__ float s_x[32][NDIM];

    const int warp = threadIdx.x >> 5;
    const int lane = threadIdx.x & 31;
    const int base = blockIdx.x * 32;

    for (int i = threadIdx.x; i < 32 * NDIM; i += blockDim.x) {
        int r = i >> 7;
        int c = i & (NDIM - 1);
        int row = base + r;
        s_x[r][c] = (row < n_rows) ? xt[(size_t)row * NDIM + c] : 0.0f;
    }
    __syncthreads();

    const int r0  = warp * 4;
    const int col = lane * 4;

    float4 a0 = make_float4(0.f, 0.f, 0.f, 0.f);
    float4 a1 = a0, a2 = a0, a3 = a0;

#define FMA_ROW(acc, xv)                                             \
    acc.x += xv.x * w0.x + xv.y * w1.x + xv.z * w2.x + xv.w * w3.x;  \
    acc.y += xv.x * w0.y + xv.y * w1.y + xv.z * w2.y + xv.w * w3.y;  \
    acc.z += xv.x * w0.z + xv.y * w1.z + xv.z * w2.z + xv.w * w3.z;  \
    acc.w += xv.x * w0.w + xv.y * w1.w + xv.z * w2.w + xv.w * w3.w;

#pragma unroll 8
    for (int f = 0; f < NDIM; f += 4) {
        float4 w0 = *(const float4*)(g_Wt + (f + 0) * NDIM + col);
        float4 w1 = *(const float4*)(g_Wt + (f + 1) * NDIM + col);
        float4 w2 = *(const float4*)(g_Wt + (f + 2) * NDIM + col);
        float4 w3 = *(const float4*)(g_Wt + (f + 3) * NDIM + col);

        float4 x0 = *(const float4*)&s_x[r0 + 0][f];
        float4 x1 = *(const float4*)&s_x[r0 + 1][f];
        float4 x2 = *(const float4*)&s_x[r0 + 2][f];
        float4 x3 = *(const float4*)&s_x[r0 + 3][f];

        FMA_ROW(a0, x0)
        FMA_ROW(a1, x1)
        FMA_ROW(a2, x2)
        FMA_ROW(a3, x3)
    }
#undef FMA_ROW

    // store fp16 (4 halves = 8 bytes per row-chunk)
#define STORE_ROW(acc, rr)                                                    \
    {                                                                         \
        int row = base + r0 + rr;                                             \
        if (row < n_rows) {                                                   \
            __half2 h0 = __floats2half2_rn(acc.x, acc.y);                     \
            __half2 h1 = __floats2half2_rn(acc.z, acc.w);                     \
            __half2* p = (__half2*)(g_z_h + (size_t)row * NDIM + col);        \
            p[0] = h0; p[1] = h1;                                             \
        }                                                                     \
    }
    STORE_ROW(a0, 0)
    STORE_ROW(a1, 1)
    STORE_ROW(a2, 2)
    STORE_ROW(a3, 3)
#undef STORE_ROW
}

// ---------------------------------------------------------------------------
// Kernel 4: per-edge dot on fp16 tables.
// 16 lanes per edge, 8 edges per warp (4 unrolled pairs), all loads hoisted.
// ---------------------------------------------------------------------------
__device__ __forceinline__ float dot8h(float4 a, float4 v) {
    const __half2* ah = (const __half2*)&a;
    const __half2* vh = (const __half2*)&v;
    float acc = 0.f;
#pragma unroll
    for (int i = 0; i < 4; i++) {
        float2 af = __half22float2(ah[i]);
        float2 vf = __half22float2(vh[i]);
        acc += af.x * vf.x + af.y * vf.y;
    }
    return acc;
}

#define EDGES_PER_WARP 8

__global__ void __launch_bounds__(256) edge_dot_kernel(
    const void* __restrict__ eli_raw,
    const float* __restrict__ bias,
    float* __restrict__ out,
    int E, int N) {
    const int gwarp = (blockIdx.x * blockDim.x + threadIdx.x) >> 5;
    const int lane  = threadIdx.x & 31;
    const int half  = lane >> 4;     // 0/1: which edge of the pair
    const int sub   = lane & 15;     // position within the 16-lane group

    const int e0 = gwarp * EDGES_PER_WARP;
    if (e0 >= E) return;

    const int is64 = g_idx_is64;
    const long long* eli64 = (const long long*)eli_raw;
    const int*       eli32 = (const int*)eli_raw;

    int eidx[4];
    long long sIdx[4], tIdx[4];
#pragma unroll
    for (int j = 0; j < 4; j++) {
        int e = e0 + 2 * j + half;
        if (e >= E) e = E - 1;            // safe duplicate work at the tail
        eidx[j] = e;
        long long s, t;
        if (is64) { s = __ldg(&eli64[e]); t = __ldg(&eli64[(long long)E + e]); }
        else      { s = __ldg(&eli32[e]); t = __ldg(&eli32[(long long)E + e]); }
        if (s < 0) s = 0; if (s >= N) s = N - 1;
        if (t < 0) t = 0; if (t >= N) t = N - 1;
        sIdx[j] = s; tIdx[j] = t;
    }

    // hoist all 8 vector loads (8 x 16B per lane) for max MLP
    float4 a[4], v[4];
#pragma unroll
    for (int j = 0; j < 4; j++) {
        a[j] = __ldg((const float4*)(g_xs_h + ((size_t)sIdx[j] << 7) + (sub << 3)));
        v[j] = __ldg((const float4*)(g_z_h  + ((size_t)tIdx[j] << 7) + (sub << 3)));
    }

    const float bv = __ldg(bias);

#pragma unroll
    for (int j = 0; j < 4; j++) {
        float acc = dot8h(a[j], v[j]);
#pragma unroll
        for (int o = 8; o > 0; o >>= 1)
            acc += __shfl_down_sync(0xFFFFFFFFu, acc, o, 16);
        if (sub == 0 && (e0 + 2 * j + half) < E)
            out[eidx[j]] = acc + bv;
    }
}

// ---------------------------------------------------------------------------
extern "C" void kernel_launch(void* const* d_in, const int* in_sizes, int n_in,
                              void* d_out, int out_size) {
    // Identify inputs by element count:
    //   W: 16384; b: 1; edges: 2*E; features: N*128 (x_source first, then x_target)
    const float* x_source = nullptr;
    const float* x_target = nullptr;
    const void*  eli      = nullptr;
    const float* W        = nullptr;
    const float* bias     = nullptr;
    int N = 0;
    const int E = out_size;

    for (int i = 0; i < n_in; i++) {
        int sz = in_sizes[i];
        if (sz == NDIM * NDIM)      W    = (const float*)d_in[i];
        else if (sz == 1)           bias = (const float*)d_in[i];
        else if (sz == 2 * E)       eli  = d_in[i];
        else {
            if (!x_source) { x_source = (const float*)d_in[i]; N = sz / NDIM; }
            else           { x_target = (const float*)d_in[i]; }
        }
    }

    float* out = (float*)d_out;

    // 0) detect index dtype
    int nwords = 2 * E; if (nwords > 4096) nwords = 4096;
    detect_idx_kernel<<<1, 256>>>((const int*)eli, nwords);

    // 1) Wt = W^T
    transpose_W_kernel<<<NDIM, NDIM>>>(W);

    // 2) x_source -> fp16
    int n_elem4 = (N * NDIM) / 4;
    convert_xs_kernel<<<(n_elem4 + 255) / 256, 256>>>(x_source, n_elem4);

    // 3) z = x_target @ W^T (fp16 store)
    gemm_zt_kernel<<<(N + 31) / 32, 256>>>(x_target, N);

    // 4) per-edge gather + dot (8 edges/warp -> 64 edges per 256-thr block)
    int warps_needed = (E + EDGES_PER_WARP - 1) / EDGES_PER_WARP;
    int nblocks = (warps_needed + 7) / 8;
    edge_dot_kernel<<<nblocks, 256>>>(eli, bias, out, E, N);
}